// round 11
// baseline (speedup 1.0000x reference)
#include <cuda_runtime.h>
#include <math.h>

#define NB    4      // batch
#define S     363    // sinogram length / recon grid
#define A     180    // angles
#define AH    90     // angles per half
#define W     256    // output size
#define RP    364    // table row entries, k in [0,363]

// tab2[pair][a][k] = (mid_b0, delta_b0, mid_b1, delta_b1) for batches
// (2*pair, 2*pair+1): delta = p[k]-p[k-1], mid = p[k-1]+0.5*delta, p[-1]=p[363]=0.
// Interp at q (=pos+1, round k of q-0.5): mid + t*delta, t = (q-0.5)-k.
__device__ float4 g_tab2[2][A * RP];
// angle-half partials, same layout as out: [half][n][yy][xx]
__device__ float g_part[2][NB * W * W];

// One block per (n, a) column. Spatial ramp-filter convolution, taps folded to
// immediates via full unroll:
// p[i] = 0.5*x[i] + sum_{d odd} (-2/(pi*d)^2) * (x[i-d] + x[i+d])
__global__ __launch_bounds__(384) void ramp_filter_kernel(const float* __restrict__ x) {
    const int na = blockIdx.x;
    const int n  = na / A;
    const int a  = na - n * A;

    __shared__ float xsp[S + 2 * 362];  // zeros | data | zeros
    __shared__ float ps[S + 2];         // p[-1..363], zero-padded ends

    const int t = threadIdx.x;
    if (t < 362) {
        xsp[t] = 0.0f;
        xsp[725 + t] = 0.0f;
    }
    if (t < 2) ps[t * 364] = 0.0f;      // ps[0]=p[-1]=0, ps[364]=p[363]=0
    // input layout: [n][1][s][a], a fastest
    for (int s = t; s < S; s += 384)
        xsp[362 + s] = x[(n * S + s) * A + a];
    __syncthreads();

    if (t < S) {
        const float* c = xsp + 362 + t;
        float acc = 0.5f * c[0];
        #pragma unroll
        for (int j = 0; j < 181; ++j) {
            const int d = 2 * j + 1;
            const float h = -2.0f / ((float)(M_PI * M_PI) * (float)d * (float)d);
            acc = fmaf(c[-d] + c[d], h, acc);
        }
        ps[t + 1] = acc;
    }
    __syncthreads();

    // write this batch's (mid, delta) half of the packed pair table
    float2* gr = ((float2*)&g_tab2[n >> 1][(size_t)a * RP]) + (n & 1);
    if (t < RP) {                        // k = t in [0, 363]
        const float p0 = ps[t];          // p[k-1]
        const float p1 = ps[t + 1];      // p[k]
        const float d  = p1 - p0;
        gr[2 * t] = make_float2(fmaf(0.5f, d, p0), d);
    }
}

#define CH 3                     // angles per pipeline chunk (90/3 = 30, even)
#define NCHUNK (AH / CH)
#define MAGICF 12582912.0f       // 2^23 + 2^22
#define MAGICI 0x4B400000

// grid (W, 2, 2): one block = one output row x batch-pair x angle-half.
// 2 batches per thread via ONE LDG.128 per angle. qp = xf*cos - yf*sin + 181.5;
// k = round(qp) via magic, t = qp - k in [-0.5,0.5]; value = mid + t*delta.
__global__ __launch_bounds__(256) void backproject_kernel() {
    const int yy = blockIdx.x;
    const int pr = blockIdx.y;
    const int hf = blockIdx.z;
    const int xx = threadIdx.x;
    const int abase = hf * AH;

    __shared__ float2 scb[AH];   // (cos, 181.5 - yf*sin) for angle abase+t

    const float yf = (float)(yy - 128);
    if (threadIdx.x < AH) {
        float sn, cs;
        sincosf((float)(abase + threadIdx.x) * (float)(M_PI / 180.0), &sn, &cs);
        scb[threadIdx.x] = make_float2(cs, fmaf(-yf, sn, 181.5f));
    }
    __syncthreads();

    const float xf = (float)(xx - 128);
    const float4* __restrict__ tb = g_tab2[pr] + (size_t)abase * RP;

    float accm0 = 0.f, accm1 = 0.f;
    float accd0 = 0.f, accd1 = 0.f;

    float4 va[CH], vb[CH];
    float  wa[CH], wb[CH];

    #define LOADC(c, vv, ww)                                                  \
        {                                                                     \
            const int a0 = (c) * CH;                                          \
            _Pragma("unroll")                                                 \
            for (int k = 0; k < CH; ++k) {                                    \
                const float2 cb = scb[a0 + k];                                \
                const float qp = fmaf(xf, cb.x, cb.y);   /* q - 0.5 */        \
                const float f  = qp + MAGICF;                                 \
                const float il = f - MAGICF;             /* round(qp) */      \
                ww[k] = qp - il;                         /* in [-.5,.5] */    \
                const int i = __float_as_int(f) - MAGICI;                     \
                vv[k] = __ldg(tb + (a0 + k) * RP + i);                        \
            }                                                                 \
        }

    #define ACCC(vv, ww)                                                      \
        {                                                                     \
            _Pragma("unroll")                                                 \
            for (int k = 0; k < CH; ++k) {                                    \
                accm0 += vv[k].x;                                             \
                accd0 = fmaf(ww[k], vv[k].y, accd0);                          \
                accm1 += vv[k].z;                                             \
                accd1 = fmaf(ww[k], vv[k].w, accd1);                          \
            }                                                                 \
        }

    LOADC(0, va, wa)
    LOADC(1, vb, wb)
    #pragma unroll 1
    for (int c = 0; c + 2 < NCHUNK; c += 2) {
        ACCC(va, wa)
        LOADC(c + 2, va, wa)
        ACCC(vb, wb)
        LOADC(c + 3, vb, wb)
    }
    ACCC(va, wa)
    ACCC(vb, wb)

    #undef LOADC
    #undef ACCC

    float* o = g_part[hf] + ((size_t)(2 * pr) * W * W) + (size_t)yy * W + xx;
    o[0]     = accm0 + accd0;
    o[W * W] = accm1 + accd1;
}

// out = (part0 + part1) * pi/360, fully coalesced float4.
__global__ __launch_bounds__(256) void combine_kernel(float* __restrict__ out) {
    const int i = blockIdx.x * 256 + threadIdx.x;     // float4 index
    const float4 p0 = ((const float4*)g_part[0])[i];
    const float4 p1 = ((const float4*)g_part[1])[i];
    const float sc = (float)(M_PI / 360.0);
    float4 r;
    r.x = (p0.x + p1.x) * sc;
    r.y = (p0.y + p1.y) * sc;
    r.z = (p0.z + p1.z) * sc;
    r.w = (p0.w + p1.w) * sc;
    ((float4*)out)[i] = r;
}

extern "C" void kernel_launch(void* const* d_in, const int* in_sizes, int n_in,
                              void* d_out, int out_size) {
    const float* x = (const float*)d_in[0];
    float* out = (float*)d_out;

    ramp_filter_kernel<<<NB * A, 384>>>(x);
    backproject_kernel<<<dim3(W, 2, 2), 256>>>();
    combine_kernel<<<(NB * W * W / 4) / 256, 256>>>(out);
}

// round 12
// speedup vs baseline: 1.1484x; 1.1484x over previous
#include <cuda_runtime.h>
#include <math.h>

#define NB    4      // batch
#define S     363    // sinogram length / recon grid
#define A     180    // angles
#define W     256    // output size
#define RP    364    // table row entries, k in [0,363]

// tab2[pair][a][k] = (mid_b0, delta_b0, mid_b1, delta_b1) for batches
// (2*pair, 2*pair+1): delta = p[k]-p[k-1], mid = p[k-1]+0.5*delta, p[-1]=p[363]=0.
// Interp at q (=pos+1, round k of q-0.5): mid + t*delta, t = (q-0.5)-k.
__device__ float4 g_tab2[2][A * RP];

// One block per (n, a) column. Spatial ramp-filter convolution, taps folded to
// immediates via full unroll:
// p[i] = 0.5*x[i] + sum_{d odd} (-2/(pi*d)^2) * (x[i-d] + x[i+d])
__global__ __launch_bounds__(384) void ramp_filter_kernel(const float* __restrict__ x) {
    const int na = blockIdx.x;
    const int n  = na / A;
    const int a  = na - n * A;

    __shared__ float xsp[S + 2 * 362];  // zeros | data | zeros
    __shared__ float ps[S + 2];         // p[-1..363], zero-padded ends

    const int t = threadIdx.x;
    if (t < 362) {
        xsp[t] = 0.0f;
        xsp[725 + t] = 0.0f;
    }
    if (t < 2) ps[t * 364] = 0.0f;      // ps[0]=p[-1]=0, ps[364]=p[363]=0
    // input layout: [n][1][s][a], a fastest
    for (int s = t; s < S; s += 384)
        xsp[362 + s] = x[(n * S + s) * A + a];
    __syncthreads();

    if (t < S) {
        const float* c = xsp + 362 + t;
        float acc = 0.5f * c[0];
        #pragma unroll
        for (int j = 0; j < 181; ++j) {
            const int d = 2 * j + 1;
            const float h = -2.0f / ((float)(M_PI * M_PI) * (float)d * (float)d);
            acc = fmaf(c[-d] + c[d], h, acc);
        }
        ps[t + 1] = acc;
    }
    __syncthreads();

    // write this batch's (mid, delta) half of the packed pair table
    float2* gr = ((float2*)&g_tab2[n >> 1][(size_t)a * RP]) + (n & 1);
    if (t < RP) {                        // k = t in [0, 363]
        const float p0 = ps[t];          // p[k-1]
        const float p1 = ps[t + 1];      // p[k]
        const float d  = p1 - p0;
        gr[2 * t] = make_float2(fmaf(0.5f, d, p0), d);
    }
}

#define CH 3                     // angles per pipeline chunk (180/3 = 60, even)
#define NCHUNK (A / CH)
#define MAGICF 12582912.0f       // 2^23 + 2^22
#define MAGICI 0x4B400000

// grid (8, 32, 2): block = 32(x) x 8(y) spatial tile of one batch-pair.
// Warp = 8(x) x 4(y) patch -> per-angle lane footprint ~7 table entries,
// and all 8 warps of a block share one ~640B window per angle (L1 reuse).
// qp = xf*cos - yf*sin + 181.5; k = round(qp); value = mid + (qp-k)*delta.
__global__ __launch_bounds__(256) void backproject_kernel(float* __restrict__ out) {
    const int pr = blockIdx.z;
    const int x0 = blockIdx.x * 32;
    const int y0 = blockIdx.y * 8;
    const int tid = threadIdx.x;
    const int w = tid >> 5, l = tid & 31;

    const int xx = x0 + ((w & 3) << 3) + (l & 7);
    const int yy = y0 + ((w >> 2) << 2) + (l >> 3);

    __shared__ float2 sc2[A];    // (cos, sin)

    if (tid < A) {
        float sn, cs;
        sincosf((float)tid * (float)(M_PI / 180.0), &sn, &cs);
        sc2[tid] = make_float2(cs, sn);
    }
    __syncthreads();

    const float xf = (float)(xx - 128);
    const float yf = (float)(yy - 128);
    const float4* __restrict__ tb = g_tab2[pr];

    float accm0 = 0.f, accm1 = 0.f;
    float accd0 = 0.f, accd1 = 0.f;

    float4 va[CH], vb[CH];
    float  wa[CH], wb[CH];

    #define LOADC(c, vv, ww)                                                  \
        {                                                                     \
            const int a0 = (c) * CH;                                          \
            _Pragma("unroll")                                                 \
            for (int k = 0; k < CH; ++k) {                                    \
                const float2 cb = sc2[a0 + k];                                \
                const float qp = fmaf(xf, cb.x, fmaf(-yf, cb.y, 181.5f));     \
                const float f  = qp + MAGICF;                                 \
                const float il = f - MAGICF;             /* round(qp) */      \
                ww[k] = qp - il;                         /* in [-.5,.5] */    \
                const int i = __float_as_int(f) - MAGICI;                     \
                vv[k] = __ldg(tb + (a0 + k) * RP + i);                        \
            }                                                                 \
        }

    #define ACCC(vv, ww)                                                      \
        {                                                                     \
            _Pragma("unroll")                                                 \
            for (int k = 0; k < CH; ++k) {                                    \
                accm0 += vv[k].x;                                             \
                accd0 = fmaf(ww[k], vv[k].y, accd0);                          \
                accm1 += vv[k].z;                                             \
                accd1 = fmaf(ww[k], vv[k].w, accd1);                          \
            }                                                                 \
        }

    LOADC(0, va, wa)
    LOADC(1, vb, wb)
    #pragma unroll 1
    for (int c = 0; c + 2 < NCHUNK; c += 2) {
        ACCC(va, wa)
        LOADC(c + 2, va, wa)
        ACCC(vb, wb)
        LOADC(c + 3, vb, wb)
    }
    ACCC(va, wa)
    ACCC(vb, wb)

    #undef LOADC
    #undef ACCC

    const float sc = (float)(M_PI / 360.0);
    float* o = out + ((size_t)(2 * pr) * W * W) + (size_t)yy * W + xx;
    o[0]     = (accm0 + accd0) * sc;
    o[W * W] = (accm1 + accd1) * sc;
}

extern "C" void kernel_launch(void* const* d_in, const int* in_sizes, int n_in,
                              void* d_out, int out_size) {
    const float* x = (const float*)d_in[0];
    float* out = (float*)d_out;

    ramp_filter_kernel<<<NB * A, 384>>>(x);
    backproject_kernel<<<dim3(8, 32, 2), 256>>>(out);
}